// round 15
// baseline (speedup 1.0000x reference)
#include <cuda_runtime.h>
#include <cuda_fp16.h>
#include <cstdint>
#include <math.h>

// Problem constants (B=4, L=4096, D=1024)
#define BB 4
#define LL 4096
#define DD 1024
#define MM (BB * LL)      // 16384 rows
#define KDIM (2 * DD)     // 2048
#define BLD (BB * LL * DD)
#define NCHUNK 128
#define CHUNK 32          // NCHUNK * CHUNK == LL

// GEMM tiling: BM=BN=128, 4 warps (128 thr), 64x64 warp tiles, ST=3, 2 CTA/SM
#define BM 128
#define BN 128
#define BKC 64               // k per stage (64 fp16 = 128B rows)
#define ST 3                 // pipeline stages
#define NCHG (KDIM / BKC)    // 32 k-chunks
#define STAGE_BYTES 32768    // A 16KB + B 16KB
#define NTHR 128

// epilogue staging row stride in floats (multiple of 4 for float4 alignment)
#define EPS 132

// ---- device scratch (no cudaMalloc allowed) ----
__device__ float g_sums[BB * NCHUNK * DD];
__device__ __align__(256) __half g_A16[(size_t)MM * KDIM];    // fp16 concat(X, AVG)
__device__ __align__(256) __half g_W16[(size_t)KDIM * KDIM];  // fp16 permuted W

// ---------------- helpers ----------------
__device__ __forceinline__ uint32_t smem_u32(const void* p) {
    uint32_t a;
    asm("{ .reg .u64 t; cvta.to.shared.u64 t, %1; cvt.u32.u64 %0, t; }" : "=r"(a) : "l"(p));
    return a;
}
__device__ __forceinline__ void cp16(uint32_t dst, const void* src) {
    asm volatile("cp.async.cg.shared.global [%0], [%1], 16;" :: "r"(dst), "l"(src));
}
__device__ __forceinline__ void cp_commit() {
    asm volatile("cp.async.commit_group;" ::: "memory");
}
template <int N>
__device__ __forceinline__ void cp_wait() {
    asm volatile("cp.async.wait_group %0;" :: "n"(N) : "memory");
}
__device__ __forceinline__ void ldsm4(uint32_t& r0, uint32_t& r1, uint32_t& r2,
                                      uint32_t& r3, uint32_t addr) {
    asm volatile("ldmatrix.sync.aligned.m8n8.x4.shared.b16 {%0,%1,%2,%3}, [%4];"
                 : "=r"(r0), "=r"(r1), "=r"(r2), "=r"(r3) : "r"(addr));
}
__device__ __forceinline__ void mma16816(float& c0, float& c1, float& c2, float& c3,
                                         uint32_t a0, uint32_t a1, uint32_t a2, uint32_t a3,
                                         uint32_t b0, uint32_t b1) {
    asm volatile(
        "mma.sync.aligned.m16n8k16.row.col.f32.f16.f16.f32 "
        "{%0,%1,%2,%3}, {%4,%5,%6,%7}, {%8,%9}, {%0,%1,%2,%3};"
        : "+f"(c0), "+f"(c1), "+f"(c2), "+f"(c3)
        : "r"(a0), "r"(a1), "r"(a2), "r"(a3), "r"(b0), "r"(b1));
}
__device__ __forceinline__ uint2 f4_to_h4(float4 v) {
    uint2 r;
    __half2 lo = __floats2half2_rn(v.x, v.y);
    __half2 hi = __floats2half2_rn(v.z, v.w);
    r.x = *(uint32_t*)&lo;
    r.y = *(uint32_t*)&hi;
    return r;
}
__device__ __forceinline__ float4 h4_to_f4(uint2 u) {
    __half2 lo = *(__half2*)&u.x;
    __half2 hi = *(__half2*)&u.y;
    return make_float4(__low2float(lo), __high2float(lo),
                       __low2float(hi), __high2float(hi));
}
__device__ __forceinline__ float sigf(float v) {
    return 1.f / (1.f + __expf(-v));
}

// ---------------- Pass A (fused, vectorized) ----------------
__global__ void prep_a(const float* __restrict__ X, const float* __restrict__ W) {
    if (blockIdx.x < 512) {
        const int c = blockIdx.x & (NCHUNK - 1);
        const int b = blockIdx.x >> 7;
        const int d = threadIdx.x * 4;
        const size_t row0 = (size_t)(b * LL + c * CHUNK);
        const float4* p = (const float4*)(X + row0 * DD + d);
        uint2* q = (uint2*)(g_A16 + row0 * KDIM + d);
        float4 s = make_float4(0.f, 0.f, 0.f, 0.f);
#pragma unroll 4
        for (int i = 0; i < CHUNK; ++i) {
            float4 v = __ldcs(p + i * (DD / 4));
            s.x += v.x; s.y += v.y; s.z += v.z; s.w += v.w;
            q[i * (KDIM / 4)] = f4_to_h4(v);
        }
        *(float4*)(g_sums + (b * NCHUNK + c) * DD + d) = s;
    } else {
        const size_t idx = (size_t)(blockIdx.x - 512) * 256 + threadIdx.x;
        const int j = (int)(idx >> 9);
        const int k4 = (int)(idx & 511);
        const int e = (j >> 1) + ((j & 1) << 10);
        float4 v = __ldcs((const float4*)(W + (size_t)e * KDIM + k4 * 4));
        *(uint2*)(g_W16 + (size_t)j * KDIM + k4 * 4) = f4_to_h4(v);
    }
}

// ---------------- Pass B: exclusive scan of chunk sums ----------------
__global__ void scan_pass_b() {
    const int t = blockIdx.x * 256 + threadIdx.x;
    const int b = t >> 8;
    const int d = (t & 255) * 4;
    float4 run = make_float4(0.f, 0.f, 0.f, 0.f);
#pragma unroll 8
    for (int c = 0; c < NCHUNK; ++c) {
        float4* p = (float4*)(g_sums + (b * NCHUNK + c) * DD + d);
        float4 v = *p;
        *p = run;
        run.x += v.x; run.y += v.y; run.z += v.z; run.w += v.w;
    }
}

// ---------------- Pass C: prefix mean (fp16 in) -> AVG fp32 + fp16 copy ------------
__global__ void scan_pass_c(float* __restrict__ AVG) {
    const int c = blockIdx.x & (NCHUNK - 1);
    const int b = blockIdx.x >> 7;
    const int d = threadIdx.x * 4;
    const size_t row0 = (size_t)(b * LL + c * CHUNK);
    const uint2* hx = (const uint2*)(g_A16 + row0 * KDIM + d);
    float4* o = (float4*)(AVG + row0 * DD + d);
    uint2* q = (uint2*)(g_A16 + row0 * KDIM + DD + d);
    float4 run = *(const float4*)(g_sums + (b * NCHUNK + c) * DD + d);
    const int l0 = c * CHUNK;
#pragma unroll 4
    for (int i = 0; i < CHUNK; ++i) {
        float4 v = h4_to_f4(hx[i * (KDIM / 4)]);
        run.x += v.x; run.y += v.y; run.z += v.z; run.w += v.w;
        const float rcp = 1.f / (float)(l0 + i + 1);
        float4 a = make_float4(run.x * rcp, run.y * rcp, run.z * rcp, run.w * rcp);
        __stcs(o + i * (DD / 4), a);
        q[i * (KDIM / 4)] = f4_to_h4(a);
    }
}

// ---------------- fp16 mma.sync GEMM + fused gating epilogue ----------------------
// grid (16, 128); 128 threads, 4 warps, 64x64 warp tiles (2 m-warps x 2 n-warps)
__global__ __launch_bounds__(NTHR, 2) void gemm_gate(
    const float* __restrict__ bias, float* __restrict__ OUT)
{
    extern __shared__ __align__(1024) char smem[];
    const uint32_t sb = smem_u32(smem);
    const int tid = threadIdx.x;
    const int lane = tid & 31;
    const int wid = tid >> 5;            // 4 warps
    const int wm = wid >> 1;             // 2 in m (64 rows each)
    const int wn = wid & 1;              // 2 in n (64 cols each)
    const int m0 = blockIdx.y * BM;
    const int n0 = blockIdx.x * BN;

    const __half* gA = g_A16 + (size_t)m0 * KDIM;
    const __half* gB = g_W16 + (size_t)n0 * KDIM;

    // stage loader: 2048 cp16 chunks over 128 threads = 16 each (8 A + 8 B)
    auto load_stage = [&](int s, int kt) {
        const uint32_t abase = sb + s * STAGE_BYTES;
        const uint32_t bbase = abase + 16384u;
        const __half* a = gA + kt * BKC;
        const __half* b = gB + kt * BKC;
#pragma unroll
        for (int i = 0; i < 8; ++i) {
            int lin = i * NTHR + tid;         // 0..1023
            int row = lin >> 3;               // 0..127
            int ch  = lin & 7;                // 16B chunk within 128B row
            uint32_t off = (uint32_t)(row * 128 + ((ch ^ (row & 7)) << 4));
            cp16(abase + off, a + (size_t)row * KDIM + ch * 8);
            cp16(bbase + off, b + (size_t)row * KDIM + ch * 8);
        }
    };

    float acc[4][8][4];
#pragma unroll
    for (int i = 0; i < 4; ++i)
#pragma unroll
        for (int j = 0; j < 8; ++j)
#pragma unroll
            for (int v = 0; v < 4; ++v) acc[i][j][v] = 0.f;

    load_stage(0, 0); cp_commit();
    load_stage(1, 1); cp_commit();

    for (int kt = 0; kt < NCHG; ++kt) {
        cp_wait<ST - 2>();
        __syncthreads();
        if (kt + 2 < NCHG) load_stage((kt + 2) % ST, kt + 2);
        cp_commit();

        const int s = kt % ST;
        const uint32_t abase = sb + s * STAGE_BYTES;
        const uint32_t bbase = abase + 16384u;

#pragma unroll
        for (int kk = 0; kk < 4; ++kk) {
            uint32_t af[4][4];
#pragma unroll
            for (int i = 0; i < 4; ++i) {
                int row = wm * 64 + i * 16 + (lane & 15);
                int ch  = kk * 2 + (lane >> 4);
                ldsm4(af[i][0], af[i][1], af[i][2], af[i][3],
                      abase + (uint32_t)(row * 128 + ((ch ^ (row & 7)) << 4)));
            }
            uint32_t bf[4][4];
#pragma unroll
            for (int jn = 0; jn < 4; ++jn) {
                int row = wn * 64 + jn * 16 + (lane & 7) + ((lane >> 4) << 3);
                int ch  = kk * 2 + ((lane >> 3) & 1);
                ldsm4(bf[jn][0], bf[jn][1], bf[jn][2], bf[jn][3],
                      bbase + (uint32_t)(row * 128 + ((ch ^ (row & 7)) << 4)));
            }
#pragma unroll
            for (int i = 0; i < 4; ++i)
#pragma unroll
                for (int j = 0; j < 8; ++j) {
                    const int jn = j >> 1, p = j & 1;
                    mma16816(acc[i][j][0], acc[i][j][1], acc[i][j][2], acc[i][j][3],
                             af[i][0], af[i][1], af[i][2], af[i][3],
                             bf[jn][p * 2], bf[jn][p * 2 + 1]);
                }
        }
    }

    // ================= coalesced gating epilogue =================
    __syncthreads();
    float* sst = (float*)smem;               // [128][EPS] floats
#pragma unroll
    for (int j = 0; j < 8; ++j) {
        const int dl = wn * 32 + j * 4 + (lane & 3);     // 0..63 local d
        const float bi  = __ldg(bias + (n0 >> 1) + dl);
        const float bfv = __ldg(bias + DD + (n0 >> 1) + dl);
#pragma unroll
        for (int i = 0; i < 4; ++i) {
#pragma unroll
            for (int h = 0; h < 2; ++h) {
                const int ml = wm * 64 + i * 16 + (lane >> 2) + h * 8;
                sst[ml * EPS + 2 * dl]     = acc[i][j][h * 2]     + bi;
                sst[ml * EPS + 2 * dl + 1] = acc[i][j][h * 2 + 1] + bfv;
            }
        }
    }
    __syncthreads();

    // Phase 2: each of 128 threads owns one full 64-d row
    {
        const int ml = tid;
        const int m  = m0 + ml;
        const int dg = (n0 >> 1);
        const float* srow = sst + ml * EPS;
        const __half* hx = g_A16 + (size_t)m * KDIM + dg;
        const __half* hv = hx + DD;
        float* orow = OUT + (size_t)m * DD + dg;
#pragma unroll 4
        for (int q = 0; q < 64; q += 4) {
            float4 pa = *(const float4*)(srow + 2 * q);
            float4 pb = *(const float4*)(srow + 2 * q + 4);
            uint2 xr = *(const uint2*)(hx + q);
            uint2 ar = *(const uint2*)(hv + q);
            __half2 x01 = *(__half2*)&xr.x, x23 = *(__half2*)&xr.y;
            __half2 a01 = *(__half2*)&ar.x, a23 = *(__half2*)&ar.y;
            float4 out;
            out.x = __low2float(x01)  * sigf(pa.x) + __low2float(a01)  * sigf(pa.y);
            out.y = __high2float(x01) * sigf(pa.z) + __high2float(a01) * sigf(pa.w);
            out.z = __low2float(x23)  * sigf(pb.x) + __low2float(a23)  * sigf(pb.y);
            out.w = __high2float(x23) * sigf(pb.z) + __high2float(a23) * sigf(pb.w);
            *(float4*)(orow + q) = out;
        }
    }
}

extern "C" void kernel_launch(void* const* d_in, const int* in_sizes, int n_in,
                              void* d_out, int out_size) {
    const float* X    = (const float*)d_in[0];
    const float* W    = (const float*)d_in[1];
    const float* bias = (const float*)d_in[2];
    float* OUT = (float*)d_out;
    float* AVG = OUT + BLD;

    static int attr_set = 0;
    const int smem_bytes = ST * STAGE_BYTES;     // 98304
    if (!attr_set) {
        cudaFuncSetAttribute(gemm_gate, cudaFuncAttributeMaxDynamicSharedMemorySize, smem_bytes);
        attr_set = 1;
    }

    prep_a<<<512 + (KDIM * KDIM) / 1024, 256>>>(X, W);
    scan_pass_b<<<4, 256>>>();
    scan_pass_c<<<512, 256>>>(AVG);

    dim3 gG(KDIM / BN, MM / BM);                 // (16, 128)
    gemm_gate<<<gG, NTHR, smem_bytes>>>(bias, OUT);
}

// round 16
// speedup vs baseline: 1.0332x; 1.0332x over previous
#include <cuda_runtime.h>
#include <cuda_fp16.h>
#include <cstdint>
#include <math.h>

// Problem constants (B=4, L=4096, D=1024)
#define BB 4
#define LL 4096
#define DD 1024
#define MM (BB * LL)      // 16384 rows
#define KDIM (2 * DD)     // 2048
#define BLD (BB * LL * DD)
#define NCHUNK 128
#define CHUNK 32          // NCHUNK * CHUNK == LL
#define NSCANB 512        // scan-role blocks in fused kernel

// GEMM tiling (proven config: ST=3, 2 CTA/SM, 64x32 warp tiles)
#define BM 128
#define BN 128
#define BKC 64               // k per stage (64 fp16 = 128B rows)
#define ST 3                 // pipeline stages
#define NCHG (KDIM / BKC)    // 32 k-chunks
#define STAGE_BYTES 32768    // A 16KB + B 16KB

// epilogue staging row stride in floats (multiple of 4 for float4 alignment)
#define EPS 132

// ---- device scratch (no cudaMalloc allowed) ----
__device__ float g_sums[BB * NCHUNK * DD];
__device__ int g_done;                                        // scan_c completion flag
__device__ __align__(256) __half g_A16[(size_t)MM * KDIM];    // fp16 concat(X, AVG)
__device__ __align__(256) __half g_W16[(size_t)KDIM * KDIM];  // fp16 permuted W

// ---------------- helpers ----------------
__device__ __forceinline__ uint32_t smem_u32(const void* p) {
    uint32_t a;
    asm("{ .reg .u64 t; cvta.to.shared.u64 t, %1; cvt.u32.u64 %0, t; }" : "=r"(a) : "l"(p));
    return a;
}
__device__ __forceinline__ void cp16(uint32_t dst, const void* src) {
    asm volatile("cp.async.cg.shared.global [%0], [%1], 16;" :: "r"(dst), "l"(src));
}
__device__ __forceinline__ void cp_commit() {
    asm volatile("cp.async.commit_group;" ::: "memory");
}
template <int N>
__device__ __forceinline__ void cp_wait() {
    asm volatile("cp.async.wait_group %0;" :: "n"(N) : "memory");
}
__device__ __forceinline__ void ldsm4(uint32_t& r0, uint32_t& r1, uint32_t& r2,
                                      uint32_t& r3, uint32_t addr) {
    asm volatile("ldmatrix.sync.aligned.m8n8.x4.shared.b16 {%0,%1,%2,%3}, [%4];"
                 : "=r"(r0), "=r"(r1), "=r"(r2), "=r"(r3) : "r"(addr));
}
__device__ __forceinline__ void mma16816(float& c0, float& c1, float& c2, float& c3,
                                         uint32_t a0, uint32_t a1, uint32_t a2, uint32_t a3,
                                         uint32_t b0, uint32_t b1) {
    asm volatile(
        "mma.sync.aligned.m16n8k16.row.col.f32.f16.f16.f32 "
        "{%0,%1,%2,%3}, {%4,%5,%6,%7}, {%8,%9}, {%0,%1,%2,%3};"
        : "+f"(c0), "+f"(c1), "+f"(c2), "+f"(c3)
        : "r"(a0), "r"(a1), "r"(a2), "r"(a3), "r"(b0), "r"(b1));
}
__device__ __forceinline__ uint2 f4_to_h4(float4 v) {
    uint2 r;
    __half2 lo = __floats2half2_rn(v.x, v.y);
    __half2 hi = __floats2half2_rn(v.z, v.w);
    r.x = *(uint32_t*)&lo;
    r.y = *(uint32_t*)&hi;
    return r;
}
__device__ __forceinline__ float4 h4_to_f4(uint2 u) {
    __half2 lo = *(__half2*)&u.x;
    __half2 hi = *(__half2*)&u.y;
    return make_float4(__low2float(lo), __high2float(lo),
                       __low2float(hi), __high2float(hi));
}
__device__ __forceinline__ float sigf(float v) {
    return 1.f / (1.f + __expf(-v));
}

// ---------------- Pass A (fused, vectorized) ----------------
// blocks [0,512): per-chunk column sums (float4) + fp16 X copy
// blocks [512, 512+4096): W permute + fp16 convert (float4)
__global__ void prep_a(const float* __restrict__ X, const float* __restrict__ W) {
    if (blockIdx.x < 512) {
        const int c = blockIdx.x & (NCHUNK - 1);
        const int b = blockIdx.x >> 7;
        const int d = threadIdx.x * 4;
        const size_t row0 = (size_t)(b * LL + c * CHUNK);
        const float4* p = (const float4*)(X + row0 * DD + d);
        uint2* q = (uint2*)(g_A16 + row0 * KDIM + d);
        float4 s = make_float4(0.f, 0.f, 0.f, 0.f);
#pragma unroll 4
        for (int i = 0; i < CHUNK; ++i) {
            float4 v = __ldcs(p + i * (DD / 4));     // X is single-use: stream
            s.x += v.x; s.y += v.y; s.z += v.z; s.w += v.w;
            q[i * (KDIM / 4)] = f4_to_h4(v);
        }
        *(float4*)(g_sums + (b * NCHUNK + c) * DD + d) = s;
    } else {
        const size_t idx = (size_t)(blockIdx.x - 512) * 256 + threadIdx.x;  // float4 index
        const int j = (int)(idx >> 9);
        const int k4 = (int)(idx & 511);
        const int e = (j >> 1) + ((j & 1) << 10);
        float4 v = __ldcs((const float4*)(W + (size_t)e * KDIM + k4 * 4));
        *(uint2*)(g_W16 + (size_t)j * KDIM + k4 * 4) = f4_to_h4(v);
    }
}

// ---------------- Pass B: exclusive scan of chunk sums + flag reset ----------------
__global__ void scan_pass_b() {
    if (blockIdx.x == 0 && threadIdx.x == 0) g_done = 0;   // reset for this replay
    const int t = blockIdx.x * 256 + threadIdx.x;          // 0..1023
    const int b = t >> 8;
    const int d = (t & 255) * 4;
    float4 run = make_float4(0.f, 0.f, 0.f, 0.f);
#pragma unroll 8
    for (int c = 0; c < NCHUNK; ++c) {
        float4* p = (float4*)(g_sums + (b * NCHUNK + c) * DD + d);
        float4 v = *p;
        *p = run;
        run.x += v.x; run.y += v.y; run.z += v.z; run.w += v.w;
    }
}

// ---------------- Fused: scan_c (bids 0..511) + GEMM (bids 512..2559) --------------
// Scan blocks schedule first (lowest bids -> wave 1), finish in ~20us, set g_done.
// GEMM blocks only need the AVG half of g_A16 from k-chunk 16 (prefetched at
// kt==14, >20us into each CTA) -> they poll g_done once at kt==14.
__global__ __launch_bounds__(256, 2) void gemm_gate(
    const float* __restrict__ bias, float* __restrict__ OUT)
{
    if (blockIdx.x < NSCANB) {
        // ================== scan_c role ==================
        float* AVG = OUT + BLD;
        const int c = blockIdx.x & (NCHUNK - 1);
        const int b = blockIdx.x >> 7;
        const int d = threadIdx.x * 4;
        const size_t row0 = (size_t)(b * LL + c * CHUNK);
        const uint2* hx = (const uint2*)(g_A16 + row0 * KDIM + d);    // fp16 X
        float4* o = (float4*)(AVG + row0 * DD + d);
        uint2* q = (uint2*)(g_A16 + row0 * KDIM + DD + d);
        float4 run = *(const float4*)(g_sums + (b * NCHUNK + c) * DD + d);
        const int l0 = c * CHUNK;
#pragma unroll 4
        for (int i = 0; i < CHUNK; ++i) {
            float4 v = h4_to_f4(hx[i * (KDIM / 4)]);
            run.x += v.x; run.y += v.y; run.z += v.z; run.w += v.w;
            const float rcp = 1.f / (float)(l0 + i + 1);
            float4 a = make_float4(run.x * rcp, run.y * rcp, run.z * rcp, run.w * rcp);
            __stcs(o + i * (DD / 4), a);             // AVG output: streaming store
            q[i * (KDIM / 4)] = f4_to_h4(a);
        }
        __threadfence();
        __syncthreads();
        if (threadIdx.x == 0) atomicAdd(&g_done, 1);
        return;
    }

    // ================== GEMM role (R12 mainloop verbatim) ==================
    extern __shared__ __align__(1024) char smem[];
    const uint32_t sb = smem_u32(smem);
    const int tid = threadIdx.x;
    const int lane = tid & 31;
    const int wid = tid >> 5;            // 8 warps
    const int wm = wid & 1;              // 2 in m (64 each)
    const int wn = wid >> 1;             // 4 in n (32 each)
    const int bid2 = blockIdx.x - NSCANB;
    const int m0 = (bid2 >> 4) * BM;
    const int n0 = (bid2 & 15) * BN;

    const __half* gA = g_A16 + (size_t)m0 * KDIM;
    const __half* gB = g_W16 + (size_t)n0 * KDIM;

    auto load_stage = [&](int s, int kt) {
        const uint32_t abase = sb + s * STAGE_BYTES;
        const uint32_t bbase = abase + 16384u;
        const __half* a = gA + kt * BKC;
        const __half* b = gB + kt * BKC;
#pragma unroll
        for (int i = 0; i < 4; ++i) {
            int lin = i * 256 + tid;          // 0..1023
            int row = lin >> 3;               // 0..127
            int ch  = lin & 7;                // 16B chunk within 128B row
            uint32_t off = (uint32_t)(row * 128 + ((ch ^ (row & 7)) << 4));
            cp16(abase + off, a + (size_t)row * KDIM + ch * 8);
            cp16(bbase + off, b + (size_t)row * KDIM + ch * 8);
        }
    };

    float acc[4][4][4];
#pragma unroll
    for (int i = 0; i < 4; ++i)
#pragma unroll
        for (int j = 0; j < 4; ++j)
#pragma unroll
            for (int v = 0; v < 4; ++v) acc[i][j][v] = 0.f;

    load_stage(0, 0); cp_commit();
    load_stage(1, 1); cp_commit();

    for (int kt = 0; kt < NCHG; ++kt) {
        cp_wait<ST - 2>();
        __syncthreads();
        if (kt == 14) {
            // next prefetch (kt+2 == 16) reads the AVG half -> wait for scan blocks
            if (tid == 0) {
                while (*(volatile int*)&g_done < NSCANB) {}
                __threadfence();
            }
            __syncthreads();
        }
        if (kt + 2 < NCHG) load_stage((kt + 2) % ST, kt + 2);
        cp_commit();

        const int s = kt % ST;
        const uint32_t abase = sb + s * STAGE_BYTES;
        const uint32_t bbase = abase + 16384u;

#pragma unroll
        for (int kk = 0; kk < 4; ++kk) {
            uint32_t af[4][4];
#pragma unroll
            for (int i = 0; i < 4; ++i) {
                int row = wm * 64 + i * 16 + (lane & 15);
                int ch  = kk * 2 + (lane >> 4);
                ldsm4(af[i][0], af[i][1], af[i][2], af[i][3],
                      abase + (uint32_t)(row * 128 + ((ch ^ (row & 7)) << 4)));
            }
            uint32_t bf[2][4];
#pragma unroll
            for (int jn = 0; jn < 2; ++jn) {
                int row = wn * 32 + jn * 16 + (lane & 7) + ((lane >> 4) << 3);
                int ch  = kk * 2 + ((lane >> 3) & 1);
                ldsm4(bf[jn][0], bf[jn][1], bf[jn][2], bf[jn][3],
                      bbase + (uint32_t)(row * 128 + ((ch ^ (row & 7)) << 4)));
            }
#pragma unroll
            for (int i = 0; i < 4; ++i)
#pragma unroll
                for (int j = 0; j < 4; ++j) {
                    const int jn = j >> 1, p = j & 1;
                    mma16816(acc[i][j][0], acc[i][j][1], acc[i][j][2], acc[i][j][3],
                             af[i][0], af[i][1], af[i][2], af[i][3],
                             bf[jn][p * 2], bf[jn][p * 2 + 1]);
                }
        }
    }

    // ================= coalesced gating epilogue =================
    __syncthreads();
    float* sst = (float*)smem;               // [128][EPS] floats
#pragma unroll
    for (int j = 0; j < 4; ++j) {
        const int dl = wn * 16 + j * 4 + (lane & 3);     // 0..63 local d
        const float bi  = __ldg(bias + (n0 >> 1) + dl);
        const float bfv = __ldg(bias + DD + (n0 >> 1) + dl);
#pragma unroll
        for (int i = 0; i < 4; ++i) {
#pragma unroll
            for (int h = 0; h < 2; ++h) {
                const int ml = wm * 64 + i * 16 + (lane >> 2) + h * 8;
                sst[ml * EPS + 2 * dl]     = acc[i][j][h * 2]     + bi;
                sst[ml * EPS + 2 * dl + 1] = acc[i][j][h * 2 + 1] + bfv;
            }
        }
    }
    __syncthreads();

    {
        const int ml = tid >> 1;
        const int dh = (tid & 1) * 32;
        const int m  = m0 + ml;
        const int dg = (n0 >> 1) + dh;
        const float* srow = sst + ml * EPS + 2 * dh;
        const __half* hx = g_A16 + (size_t)m * KDIM + dg;
        const __half* hv = hx + DD;
        float* orow = OUT + (size_t)m * DD + dg;
#pragma unroll 4
        for (int q = 0; q < 32; q += 4) {
            float4 pa = *(const float4*)(srow + 2 * q);
            float4 pb = *(const float4*)(srow + 2 * q + 4);
            uint2 xr = *(const uint2*)(hx + q);
            uint2 ar = *(const uint2*)(hv + q);
            __half2 x01 = *(__half2*)&xr.x, x23 = *(__half2*)&xr.y;
            __half2 a01 = *(__half2*)&ar.x, a23 = *(__half2*)&ar.y;
            float4 out;
            out.x = __low2float(x01)  * sigf(pa.x) + __low2float(a01)  * sigf(pa.y);
            out.y = __high2float(x01) * sigf(pa.z) + __high2float(a01) * sigf(pa.w);
            out.z = __low2float(x23)  * sigf(pb.x) + __low2float(a23)  * sigf(pb.y);
            out.w = __high2float(x23) * sigf(pb.z) + __high2float(a23) * sigf(pb.w);
            *(float4*)(orow + q) = out;
        }
    }
}

extern "C" void kernel_launch(void* const* d_in, const int* in_sizes, int n_in,
                              void* d_out, int out_size) {
    const float* X    = (const float*)d_in[0];
    const float* W    = (const float*)d_in[1];
    const float* bias = (const float*)d_in[2];
    float* OUT = (float*)d_out;

    static int attr_set = 0;
    const int smem_bytes = ST * STAGE_BYTES;     // 98304
    if (!attr_set) {
        cudaFuncSetAttribute(gemm_gate, cudaFuncAttributeMaxDynamicSharedMemorySize, smem_bytes);
        attr_set = 1;
    }

    prep_a<<<512 + (KDIM * KDIM) / 1024, 256>>>(X, W);
    scan_pass_b<<<4, 256>>>();
    gemm_gate<<<NSCANB + 2048, 256, smem_bytes>>>(bias, OUT);   // scan_c fused in
}